// round 15
// baseline (speedup 1.0000x reference)
#include <cuda_runtime.h>
#include <cuda_fp16.h>
#include <stdint.h>

// ======================= constants =======================
static constexpr int NLAYERS = 8;
static constexpr int HID = 128;
static constexpr int BATCH = 262144;
static constexpr int NT = 256;             // 8 warps (2/SMSP)
static constexpr int MTILE = 256;          // 8 warps x M=32 per warp (2 M-sets of 16)
static constexpr int NBLK = BATCH / MTILE; // 1024

// padded weight image: row = 136 halves (272B) -> conflict-free ldmatrix
static constexpr int WROW = 136;
static constexpr int WIMG_HALVES = HID * WROW;      // 17408
static constexpr int WIMG_BYTES = WIMG_HALVES * 2;  // 34816
__device__ __align__(16) __half g_wh[NLAYERS * WIMG_HALVES];

// smem layout (x stored as fp16, row stride 136 halves = 272 B)
static constexpr uint32_t XROWH = 136;
static constexpr uint32_t XROWB = XROWH * 2;              // 272 bytes
static constexpr uint32_t OF_X = 0;
static constexpr uint32_t X_BYTES = MTILE * XROWB;        // 69632
static constexpr uint32_t OF_W0 = X_BYTES;                // 69632
static constexpr uint32_t OF_W1 = OF_W0 + WIMG_BYTES;     // 104448
static constexpr uint32_t OF_B0 = OF_W1 + WIMG_BYTES;     // 139264
static constexpr uint32_t OF_B1 = OF_B0 + 512;            // 139776
static constexpr uint32_t SMEM_BYTES = OF_B1 + 512;       // 140288

// ======================= PTX helpers (baseline compute_103-safe) =======================
__device__ __forceinline__ uint32_t smem_to_u32(const void* p) {
    uint32_t a;
    asm("{ .reg .u64 t; cvta.to.shared.u64 t, %1; cvt.u32.u64 %0, t; }" : "=r"(a) : "l"(p));
    return a;
}

#define CP_ASYNC16(dst, src) \
    asm volatile("cp.async.cg.shared.global [%0], [%1], 16;" :: "r"(dst), "l"(src))
#define CP_COMMIT() asm volatile("cp.async.commit_group;")
#define CP_WAIT0()  asm volatile("cp.async.wait_group 0;")

#define LDSM_X4(r0, r1, r2, r3, addr) \
    asm volatile("ldmatrix.sync.aligned.m8n8.x4.shared.b16 {%0,%1,%2,%3}, [%4];" \
                 : "=r"(r0), "=r"(r1), "=r"(r2), "=r"(r3) : "r"(addr))

#define MMA16816(d, a, b0_, b1_) \
    asm volatile("mma.sync.aligned.m16n8k16.row.col.f32.f16.f16.f32 " \
                 "{%0,%1,%2,%3}, {%4,%5,%6,%7}, {%8,%9}, {%0,%1,%2,%3};" \
                 : "+f"((d)[0]), "+f"((d)[1]), "+f"((d)[2]), "+f"((d)[3]) \
                 : "r"((a)[0]), "r"((a)[1]), "r"((a)[2]), "r"((a)[3]), \
                   "r"(b0_), "r"(b1_))

#define LDS32(r, addr) \
    asm volatile("ld.shared.b32 %0, [%1];" : "=r"(r) : "r"(addr))

// pack fp32 pair -> fp16x2
__device__ __forceinline__ uint32_t pack2(float v0, float v1) {
    __half2 h = __floats2half2_rn(v0, v1);
    return *reinterpret_cast<uint32_t*>(&h);
}
__device__ __forceinline__ uint32_t hadd2u(uint32_t a, uint32_t b) {
    __half2 r = __hadd2(*reinterpret_cast<__half2*>(&a), *reinterpret_cast<__half2*>(&b));
    return *reinterpret_cast<uint32_t*>(&r);
}

// ======================= prep: fp32 weights -> padded fp16 image =======================
__global__ void ElasticMLP_prep(const float* __restrict__ w) {
    int i = blockIdx.x * blockDim.x + threadIdx.x;
    if (i >= NLAYERS * WIMG_HALVES) return;
    int l = i / WIMG_HALVES;
    int rem = i - l * WIMG_HALVES;
    int n = rem / WROW;
    int k = rem - n * WROW;
    float v = (k < HID) ? w[(l * HID + n) * HID + k] : 0.0f;
    g_wh[i] = __float2half_rn(v);
}

// ======================= main fused MLP =======================
__global__ void __launch_bounds__(NT, 1)
ElasticMLP_main(const float* __restrict__ x, const float* __restrict__ b,
                float* __restrict__ out) {
    extern __shared__ __align__(16) char sm[];
    const uint32_t smu = smem_to_u32(sm);

    const int tid = threadIdx.x;
    const int lane = tid & 31;
    const int wid = tid >> 5;
    const int rw = wid * 16;
    const int qr = lane >> 2;         // 0..7
    const int qc = (lane & 3) * 2;    // 0,2,4,6

    // ---- stage layer-0 weights + bias (cp.async), x tile converted to fp16 ----
    {
        const char* wsrc = reinterpret_cast<const char*>(g_wh);
        for (int i = tid; i < WIMG_BYTES / 16; i += NT)
            CP_ASYNC16(smu + OF_W0 + (uint32_t)(i * 16), wsrc + i * 16);
        if (tid < 32) CP_ASYNC16(smu + OF_B0 + (uint32_t)(tid * 16), b + tid * 4);
        CP_COMMIT();

        const float4* xg = reinterpret_cast<const float4*>(x + (size_t)blockIdx.x * (MTILE * HID));
        for (int i = tid; i < MTILE * (HID / 4); i += NT) {
            int r = i >> 5, ch = i & 31;
            float4 v = xg[i];
            uint2 pk = make_uint2(pack2(v.x, v.y), pack2(v.z, v.w));
            *reinterpret_cast<uint2*>(sm + OF_X + r * XROWB + ch * 8) = pk;
        }
        CP_WAIT0();
    }
    __syncthreads();

    // ---- build layer-0 A fragments; keep persistent X for skip-adds ----
    uint32_t A[2][8][4];
    uint32_t X[2][8][4];
    #pragma unroll
    for (int ms = 0; ms < 2; ms++) {
        const int rbase = ms * 128 + rw + qr;
        #pragma unroll
        for (int kt = 0; kt < 8; kt++) {
            const uint32_t a0 = smu + OF_X + (uint32_t)(rbase * XROWB + (kt * 16 + qc) * 2);
            LDS32(X[ms][kt][0], a0);
            LDS32(X[ms][kt][1], a0 + 8 * XROWB);
            LDS32(X[ms][kt][2], a0 + 16);
            LDS32(X[ms][kt][3], a0 + 8 * XROWB + 16);
            A[ms][kt][0] = X[ms][kt][0];
            A[ms][kt][1] = X[ms][kt][1];
            A[ms][kt][2] = X[ms][kt][2];
            A[ms][kt][3] = X[ms][kt][3];
        }
    }

    // ldmatrix.x4 per-lane address offset
    const int g = lane >> 3, rsub = lane & 7;
    const uint32_t lds_off =
        (uint32_t)(((((g >= 2) ? 8 : 0) + rsub) * WROW + (g & 1) * 8) * 2);

    #pragma unroll 1
    for (int l = 0; l < NLAYERS; l++) {
        if (l + 1 < NLAYERS) {
            const char* wsrc = reinterpret_cast<const char*>(g_wh + (size_t)(l + 1) * WIMG_HALVES);
            const uint32_t dstW = smu + (((l + 1) & 1) ? OF_W1 : OF_W0);
            for (int i = tid; i < WIMG_BYTES / 16; i += NT)
                CP_ASYNC16(dstW + (uint32_t)(i * 16), wsrc + i * 16);
            if (tid < 32)
                CP_ASYNC16(smu + (((l + 1) & 1) ? OF_B1 : OF_B0) + (uint32_t)(tid * 16),
                           b + (l + 1) * HID + tid * 4);
            CP_COMMIT();
        }

        const uint32_t wbase = smu + ((l & 1) ? OF_W1 : OF_W0) + lds_off;
        const float* bs = reinterpret_cast<const float*>(sm + ((l & 1) ? OF_B1 : OF_B0));
        const bool last = (l == NLAYERS - 1);
        const bool skip = (l > 0);

        uint32_t An[2][8][4];

        // double-buffered per-group accumulators: [parity][ms][npair][quad]
        float Dbuf[2][2][2][4];

        // ---- MMA group issue helper (macro to keep everything in registers) ----
#define MMA_GROUP(PIDX, PAR) do {                                              \
            float (*Dg)[2][4] = Dbuf[(PAR)];                                   \
            _Pragma("unroll")                                                  \
            for (int ms_ = 0; ms_ < 2; ms_++)                                  \
                _Pragma("unroll")                                              \
                for (int np_ = 0; np_ < 2; np_++) {                            \
                    Dg[ms_][np_][0] = 0.f; Dg[ms_][np_][1] = 0.f;              \
                    Dg[ms_][np_][2] = 0.f; Dg[ms_][np_][3] = 0.f;              \
                }                                                              \
            const uint32_t pb_ = wbase + (uint32_t)((PIDX) * (16 * WROW * 2)); \
            _Pragma("unroll")                                                  \
            for (int kt_ = 0; kt_ < 8; kt_++) {                                \
                uint32_t b0_, b1_, b2_, b3_;                                   \
                LDSM_X4(b0_, b1_, b2_, b3_, pb_ + (uint32_t)(kt_ * 32));       \
                MMA16816(Dg[0][0], A[0][kt_], b0_, b1_);                       \
                MMA16816(Dg[0][1], A[0][kt_], b2_, b3_);                       \
                MMA16816(Dg[1][0], A[1][kt_], b0_, b1_);                       \
                MMA16816(Dg[1][1], A[1][kt_], b2_, b3_);                       \
            }                                                                  \
        } while (0)

        // prologue: group 0
        MMA_GROUP(0, 0);

        #pragma unroll
        for (int p = 0; p < 8; p++) {
            // issue next group's MMAs BEFORE this group's epilogue (overlap)
            if (p < 7) MMA_GROUP(p + 1, (p + 1) & 1);

            float (*Dp)[2][4] = Dbuf[p & 1];

            #pragma unroll
            for (int ms = 0; ms < 2; ms++) {
                if (!last) {
                    #pragma unroll
                    for (int np = 0; np < 2; np++) {
                        const int c0 = p * 16 + np * 8 + qc;
                        float2 bb = *reinterpret_cast<const float2*>(bs + c0);
                        float v0 = fmaxf(Dp[ms][np][0] + bb.x, 0.f);
                        float v1 = fmaxf(Dp[ms][np][1] + bb.y, 0.f);
                        float v2 = fmaxf(Dp[ms][np][2] + bb.x, 0.f);
                        float v3 = fmaxf(Dp[ms][np][3] + bb.y, 0.f);
                        uint32_t h01 = pack2(v0, v1);
                        uint32_t h23 = pack2(v2, v3);
                        if (skip) {
                            h01 = hadd2u(h01, X[ms][p][2 * np]);
                            h23 = hadd2u(h23, X[ms][p][2 * np + 1]);
                        }
                        An[ms][p][2 * np]     = h01;
                        An[ms][p][2 * np + 1] = h23;
                    }
                } else {
                    const int rbase = ms * 128 + rw + qr;
                    float* og = out + ((size_t)blockIdx.x * MTILE + rbase) * HID;
                    #pragma unroll
                    for (int np = 0; np < 2; np++) {
                        const int c0 = p * 16 + np * 8 + qc;
                        float2 bb = *reinterpret_cast<const float2*>(bs + c0);
                        uint32_t xu0 = X[ms][p][2 * np];
                        uint32_t xu1 = X[ms][p][2 * np + 1];
                        float2 x0 = __half22float2(*reinterpret_cast<__half2*>(&xu0));
                        float2 x1 = __half22float2(*reinterpret_cast<__half2*>(&xu1));
                        float2 o0, o1;
                        o0.x = fmaxf(Dp[ms][np][0] + bb.x, 0.f) + x0.x;
                        o0.y = fmaxf(Dp[ms][np][1] + bb.y, 0.f) + x0.y;
                        o1.x = fmaxf(Dp[ms][np][2] + bb.x, 0.f) + x1.x;
                        o1.y = fmaxf(Dp[ms][np][3] + bb.y, 0.f) + x1.y;
                        *reinterpret_cast<float2*>(og + c0) = o0;
                        *reinterpret_cast<float2*>(og + 8 * HID + c0) = o1;
                    }
                }
            }
        }
#undef MMA_GROUP

        // ---- rotate activations, sync for next weight buffer ----
        if (!last) {
            #pragma unroll
            for (int ms = 0; ms < 2; ms++)
                #pragma unroll
                for (int kt = 0; kt < 8; kt++) {
                    A[ms][kt][0] = An[ms][kt][0];
                    A[ms][kt][1] = An[ms][kt][1];
                    A[ms][kt][2] = An[ms][kt][2];
                    A[ms][kt][3] = An[ms][kt][3];
                }
            CP_WAIT0();
            __syncthreads();
        }
    }
}

// ======================= launch =======================
extern "C" void kernel_launch(void* const* d_in, const int* in_sizes, int n_in,
                              void* d_out, int out_size) {
    const float* x = (const float*)d_in[0];
    const float* w = (const float*)d_in[1];
    const float* b = (const float*)d_in[2];
    float* out = (float*)d_out;

    ElasticMLP_prep<<<(NLAYERS * WIMG_HALVES + 255) / 256, 256>>>(w);

    cudaFuncSetAttribute(ElasticMLP_main,
                         cudaFuncAttributeMaxDynamicSharedMemorySize, SMEM_BYTES);
    ElasticMLP_main<<<NBLK, NT, SMEM_BYTES>>>(x, b, out);
}

// round 16
// speedup vs baseline: 1.0070x; 1.0070x over previous
#include <cuda_runtime.h>
#include <cuda_fp16.h>
#include <stdint.h>

// ======================= constants =======================
static constexpr int NLAYERS = 8;
static constexpr int HID = 128;
static constexpr int BATCH = 262144;
static constexpr int NT = 256;             // 8 warps (2/SMSP)
static constexpr int MTILE = 256;          // 8 warps x M=32 per warp (2 M-sets of 16)
static constexpr int NBLK = BATCH / MTILE; // 1024

// padded weight image: row = 136 halves (272B) -> conflict-free ldmatrix
static constexpr int WROW = 136;
static constexpr int WIMG_HALVES = HID * WROW;      // 17408
static constexpr int WIMG_BYTES = WIMG_HALVES * 2;  // 34816
__device__ __align__(16) __half g_wh[NLAYERS * WIMG_HALVES];

// smem layout (x stored as fp16, row stride 136 halves = 272 B)
static constexpr uint32_t XROWH = 136;
static constexpr uint32_t XROWB = XROWH * 2;              // 272 bytes
static constexpr uint32_t OF_X = 0;
static constexpr uint32_t X_BYTES = MTILE * XROWB;        // 69632
static constexpr uint32_t OF_W0 = X_BYTES;                // 69632
static constexpr uint32_t OF_W1 = OF_W0 + WIMG_BYTES;     // 104448
static constexpr uint32_t OF_B0 = OF_W1 + WIMG_BYTES;     // 139264
static constexpr uint32_t OF_B1 = OF_B0 + 512;            // 139776
static constexpr uint32_t SMEM_BYTES = OF_B1 + 512;       // 140288

// ======================= PTX helpers (baseline compute_103-safe) =======================
__device__ __forceinline__ uint32_t smem_to_u32(const void* p) {
    uint32_t a;
    asm("{ .reg .u64 t; cvta.to.shared.u64 t, %1; cvt.u32.u64 %0, t; }" : "=r"(a) : "l"(p));
    return a;
}

#define CP_ASYNC16(dst, src) \
    asm volatile("cp.async.cg.shared.global [%0], [%1], 16;" :: "r"(dst), "l"(src))
#define CP_COMMIT() asm volatile("cp.async.commit_group;")
#define CP_WAIT0()  asm volatile("cp.async.wait_group 0;")

#define LDSM_X4(r0, r1, r2, r3, addr) \
    asm volatile("ldmatrix.sync.aligned.m8n8.x4.shared.b16 {%0,%1,%2,%3}, [%4];" \
                 : "=r"(r0), "=r"(r1), "=r"(r2), "=r"(r3) : "r"(addr))

#define MMA16816(d, a, b0_, b1_) \
    asm volatile("mma.sync.aligned.m16n8k16.row.col.f32.f16.f16.f32 " \
                 "{%0,%1,%2,%3}, {%4,%5,%6,%7}, {%8,%9}, {%0,%1,%2,%3};" \
                 : "+f"((d)[0]), "+f"((d)[1]), "+f"((d)[2]), "+f"((d)[3]) \
                 : "r"((a)[0]), "r"((a)[1]), "r"((a)[2]), "r"((a)[3]), \
                   "r"(b0_), "r"(b1_))

#define LDS32(r, addr) \
    asm volatile("ld.shared.b32 %0, [%1];" : "=r"(r) : "r"(addr))

// pack fp32 pair -> fp16x2
__device__ __forceinline__ uint32_t pack2(float v0, float v1) {
    __half2 h = __floats2half2_rn(v0, v1);
    return *reinterpret_cast<uint32_t*>(&h);
}
__device__ __forceinline__ uint32_t hadd2u(uint32_t a, uint32_t b) {
    __half2 r = __hadd2(*reinterpret_cast<__half2*>(&a), *reinterpret_cast<__half2*>(&b));
    return *reinterpret_cast<uint32_t*>(&r);
}

// ======================= prep: fp32 weights -> padded fp16 image =======================
__global__ void ElasticMLP_prep(const float* __restrict__ w) {
    int i = blockIdx.x * blockDim.x + threadIdx.x;
    if (i >= NLAYERS * WIMG_HALVES) return;
    int l = i / WIMG_HALVES;
    int rem = i - l * WIMG_HALVES;
    int n = rem / WROW;
    int k = rem - n * WROW;
    float v = (k < HID) ? w[(l * HID + n) * HID + k] : 0.0f;
    g_wh[i] = __float2half_rn(v);
}

// ======================= main fused MLP =======================
__global__ void __launch_bounds__(NT, 1)
ElasticMLP_main(const float* __restrict__ x, const float* __restrict__ b,
                float* __restrict__ out) {
    extern __shared__ __align__(16) char sm[];
    const uint32_t smu = smem_to_u32(sm);

    const int tid = threadIdx.x;
    const int lane = tid & 31;
    const int wid = tid >> 5;
    const int rw = wid * 16;
    const int qr = lane >> 2;         // 0..7
    const int qc = (lane & 3) * 2;    // 0,2,4,6

    // ---- stage layer-0 weights + bias (cp.async), x tile converted to fp16 ----
    {
        const char* wsrc = reinterpret_cast<const char*>(g_wh);
        for (int i = tid; i < WIMG_BYTES / 16; i += NT)
            CP_ASYNC16(smu + OF_W0 + (uint32_t)(i * 16), wsrc + i * 16);
        if (tid < 32) CP_ASYNC16(smu + OF_B0 + (uint32_t)(tid * 16), b + tid * 4);
        CP_COMMIT();

        const float4* xg = reinterpret_cast<const float4*>(x + (size_t)blockIdx.x * (MTILE * HID));
        for (int i = tid; i < MTILE * (HID / 4); i += NT) {
            int r = i >> 5, ch = i & 31;
            float4 v = xg[i];
            uint2 pk = make_uint2(pack2(v.x, v.y), pack2(v.z, v.w));
            *reinterpret_cast<uint2*>(sm + OF_X + r * XROWB + ch * 8) = pk;
        }
        CP_WAIT0();
    }
    __syncthreads();

    // ---- build layer-0 A fragments; keep persistent X for skip-adds ----
    uint32_t A[2][8][4];
    uint32_t X[2][8][4];
    #pragma unroll
    for (int ms = 0; ms < 2; ms++) {
        const int rbase = ms * 128 + rw + qr;
        #pragma unroll
        for (int kt = 0; kt < 8; kt++) {
            const uint32_t a0 = smu + OF_X + (uint32_t)(rbase * XROWB + (kt * 16 + qc) * 2);
            LDS32(X[ms][kt][0], a0);
            LDS32(X[ms][kt][1], a0 + 8 * XROWB);
            LDS32(X[ms][kt][2], a0 + 16);
            LDS32(X[ms][kt][3], a0 + 8 * XROWB + 16);
            A[ms][kt][0] = X[ms][kt][0];
            A[ms][kt][1] = X[ms][kt][1];
            A[ms][kt][2] = X[ms][kt][2];
            A[ms][kt][3] = X[ms][kt][3];
        }
    }

    // ldmatrix.x4 per-lane address offset
    const int g = lane >> 3, rsub = lane & 7;
    const uint32_t lds_off =
        (uint32_t)(((((g >= 2) ? 8 : 0) + rsub) * WROW + (g & 1) * 8) * 2);

    #pragma unroll 1
    for (int l = 0; l < NLAYERS; l++) {
        if (l + 1 < NLAYERS) {
            const char* wsrc = reinterpret_cast<const char*>(g_wh + (size_t)(l + 1) * WIMG_HALVES);
            const uint32_t dstW = smu + (((l + 1) & 1) ? OF_W1 : OF_W0);
            for (int i = tid; i < WIMG_BYTES / 16; i += NT)
                CP_ASYNC16(dstW + (uint32_t)(i * 16), wsrc + i * 16);
            if (tid < 32)
                CP_ASYNC16(smu + (((l + 1) & 1) ? OF_B1 : OF_B0) + (uint32_t)(tid * 16),
                           b + (l + 1) * HID + tid * 4);
            CP_COMMIT();
        }

        const uint32_t wbase = smu + ((l & 1) ? OF_W1 : OF_W0) + lds_off;
        const float* bs = reinterpret_cast<const float*>(sm + ((l & 1) ? OF_B1 : OF_B0));
        const bool last = (l == NLAYERS - 1);
        const bool skip = (l > 0);

        uint32_t An[2][8][4];

        // double-buffered per-group accumulators: [parity][ms][npair][quad]
        float Dbuf[2][2][2][4];

        // one (ms,np) quarter of group PE's epilogue — interleaved between MMAs
#define EPI_UNIT(PE, MS, NP) do {                                              \
            float* Dq = Dbuf[(PE) & 1][MS][NP];                                \
            const int c0_ = (PE) * 16 + (NP) * 8 + qc;                         \
            float2 bb_ = *reinterpret_cast<const float2*>(bs + c0_);           \
            if (!last) {                                                       \
                float v0_ = fmaxf(Dq[0] + bb_.x, 0.f);                         \
                float v1_ = fmaxf(Dq[1] + bb_.y, 0.f);                         \
                float v2_ = fmaxf(Dq[2] + bb_.x, 0.f);                         \
                float v3_ = fmaxf(Dq[3] + bb_.y, 0.f);                         \
                uint32_t h01_ = pack2(v0_, v1_);                               \
                uint32_t h23_ = pack2(v2_, v3_);                               \
                if (skip) {                                                    \
                    h01_ = hadd2u(h01_, X[MS][PE][2 * (NP)]);                  \
                    h23_ = hadd2u(h23_, X[MS][PE][2 * (NP) + 1]);              \
                }                                                              \
                An[MS][PE][2 * (NP)]     = h01_;                               \
                An[MS][PE][2 * (NP) + 1] = h23_;                               \
            } else {                                                           \
                const int rbase_ = (MS) * 128 + rw + qr;                       \
                float* og_ = out + ((size_t)blockIdx.x * MTILE + rbase_) * HID;\
                uint32_t xu0_ = X[MS][PE][2 * (NP)];                           \
                uint32_t xu1_ = X[MS][PE][2 * (NP) + 1];                       \
                float2 x0_ = __half22float2(*reinterpret_cast<__half2*>(&xu0_));\
                float2 x1_ = __half22float2(*reinterpret_cast<__half2*>(&xu1_));\
                float2 o0_, o1_;                                               \
                o0_.x = fmaxf(Dq[0] + bb_.x, 0.f) + x0_.x;                     \
                o0_.y = fmaxf(Dq[1] + bb_.y, 0.f) + x0_.y;                     \
                o1_.x = fmaxf(Dq[2] + bb_.x, 0.f) + x1_.x;                     \
                o1_.y = fmaxf(Dq[3] + bb_.y, 0.f) + x1_.y;                     \
                *reinterpret_cast<float2*>(og_ + c0_) = o0_;                   \
                *reinterpret_cast<float2*>(og_ + 8 * HID + c0_) = o1_;         \
            }                                                                  \
        } while (0)

        // ---- prologue: group 0 MMAs (nothing to interleave yet) ----
        {
            float (*Dg)[2][4] = Dbuf[0];
            #pragma unroll
            for (int ms_ = 0; ms_ < 2; ms_++)
                #pragma unroll
                for (int np_ = 0; np_ < 2; np_++) {
                    Dg[ms_][np_][0] = 0.f; Dg[ms_][np_][1] = 0.f;
                    Dg[ms_][np_][2] = 0.f; Dg[ms_][np_][3] = 0.f;
                }
            #pragma unroll
            for (int kt = 0; kt < 8; kt++) {
                uint32_t b0, b1, b2, b3;
                LDSM_X4(b0, b1, b2, b3, wbase + (uint32_t)(kt * 32));
                MMA16816(Dg[0][0], A[0][kt], b0, b1);
                MMA16816(Dg[0][1], A[0][kt], b2, b3);
                MMA16816(Dg[1][0], A[1][kt], b0, b1);
                MMA16816(Dg[1][1], A[1][kt], b2, b3);
            }
        }

        // ---- steady state: group p+1 MMAs with epilogue(p) interleaved per-kt ----
        #pragma unroll
        for (int p = 0; p < 8; p++) {
            if (p < 7) {
                float (*Dg)[2][4] = Dbuf[(p + 1) & 1];
                #pragma unroll
                for (int ms_ = 0; ms_ < 2; ms_++)
                    #pragma unroll
                    for (int np_ = 0; np_ < 2; np_++) {
                        Dg[ms_][np_][0] = 0.f; Dg[ms_][np_][1] = 0.f;
                        Dg[ms_][np_][2] = 0.f; Dg[ms_][np_][3] = 0.f;
                    }
                const uint32_t pb_ = wbase + (uint32_t)((p + 1) * (16 * WROW * 2));
                #pragma unroll
                for (int kt = 0; kt < 8; kt++) {
                    uint32_t b0, b1, b2, b3;
                    LDSM_X4(b0, b1, b2, b3, pb_ + (uint32_t)(kt * 32));
                    MMA16816(Dg[0][0], A[0][kt], b0, b1);
                    MMA16816(Dg[0][1], A[0][kt], b2, b3);
                    MMA16816(Dg[1][0], A[1][kt], b0, b1);
                    MMA16816(Dg[1][1], A[1][kt], b2, b3);
                    // one epilogue quarter of the PREVIOUS group between MMA packets
                    if (kt == 1)      EPI_UNIT(p, 0, 0);
                    else if (kt == 3) EPI_UNIT(p, 0, 1);
                    else if (kt == 5) EPI_UNIT(p, 1, 0);
                    else if (kt == 7) EPI_UNIT(p, 1, 1);
                }
            } else {
                // last group: plain epilogue tail
                EPI_UNIT(7, 0, 0);
                EPI_UNIT(7, 0, 1);
                EPI_UNIT(7, 1, 0);
                EPI_UNIT(7, 1, 1);
            }
        }
#undef EPI_UNIT

        // ---- rotate activations, sync for next weight buffer ----
        if (!last) {
            #pragma unroll
            for (int ms = 0; ms < 2; ms++)
                #pragma unroll
                for (int kt = 0; kt < 8; kt++) {
                    A[ms][kt][0] = An[ms][kt][0];
                    A[ms][kt][1] = An[ms][kt][1];
                    A[ms][kt][2] = An[ms][kt][2];
                    A[ms][kt][3] = An[ms][kt][3];
                }
            CP_WAIT0();
            __syncthreads();
        }
    }
}

// ======================= launch =======================
extern "C" void kernel_launch(void* const* d_in, const int* in_sizes, int n_in,
                              void* d_out, int out_size) {
    const float* x = (const float*)d_in[0];
    const float* w = (const float*)d_in[1];
    const float* b = (const float*)d_in[2];
    float* out = (float*)d_out;

    ElasticMLP_prep<<<(NLAYERS * WIMG_HALVES + 255) / 256, 256>>>(w);

    cudaFuncSetAttribute(ElasticMLP_main,
                         cudaFuncAttributeMaxDynamicSharedMemorySize, SMEM_BYTES);
    ElasticMLP_main<<<NBLK, NT, SMEM_BYTES>>>(x, b, out);
}